// round 5
// baseline (speedup 1.0000x reference)
#include <cuda_runtime.h>
#include <stdint.h>

#define NSEG 6
#define NC   512
#define NP   16384   // 128*128
#define BINS 16

// ---------------- scratch (__device__ globals, no allocation) ----------------
__device__ float    g_maskf[NSEG * NP];        // mask expanded to fp32 0/1
__device__ int      g_pb  [NSEG * BINS];       // bin position interval begin (incl)
__device__ int      g_pe  [NSEG * BINS];       // bin position interval end   (incl)
__device__ float    g_inv [NSEG * BINS];       // 1/denom per (seg,bin)
__device__ float    g_ys  [NSEG * NC * BINS];  // pooled features
__device__ float    g_wA  [NSEG * 2048];
__device__ float    g_wB  [NSEG * 512];

// ---------------- dummies: keep ncu capture slot (4th launch) on k_pool ------
__global__ void k_nop() {}

// ---------------- n-th set bit (n < popc(bits)) ------------------------------
__device__ __forceinline__ int nth_set_bit64(uint64_t bits, int n) {
    uint64_t m = bits;
    for (int i = 0; i < n; i++) m &= m - 1;    // clear n lowest set bits
    return __ffsll((long long)m) - 1;
}

// ---------------- kernel 1: mask floats + scan + bin intervals (div-free) ----
__global__ void k_scan(const int* __restrict__ parsing) {
    const int seg = blockIdx.x;
    const int tid = threadIdx.x;
    const int lane = tid & 31, wid = tid >> 5;
    const int* ps = parsing + seg * 65536;     // [256,256] plane

    const int base_p = tid * 64;
    uint64_t bits = 0;
    #pragma unroll
    for (int j = 0; j < 64; j++) {
        int p = base_p + j;
        int h = p >> 7, w = p & 127;
        if (ps[h * 512 + w * 2] != 0) bits |= (1ull << j);   // nearest 256->128: (2h,2w)
    }
    int cnt = __popcll(bits);

    __shared__ int warp_tot[8];
    __shared__ int warp_off[8];
    __shared__ int sL;
    __shared__ int s_pb[BINS], s_pe[BINS];
    __shared__ int s_t0[BINS], s_t1[BINS];
    int x = cnt;
    #pragma unroll
    for (int off = 1; off < 32; off <<= 1) {
        int y = __shfl_up_sync(0xffffffffu, x, off);
        if (lane >= off) x += y;
    }
    if (lane == 31) warp_tot[wid] = x;
    __syncthreads();
    if (tid < 8) {
        int s = 0;
        for (int i = 0; i < tid; i++) s += warp_tot[i];
        warp_off[tid] = s;
    }
    __syncthreads();
    int excl = warp_off[wid] + x - cnt;
    if (tid == 255) sL = excl + cnt;
    __syncthreads();
    const int L = sL;

    // expand mask to fp32 (pool reads this as an L1/L2-resident float4 stream)
    {
        float* mf = g_maskf + seg * NP + base_p;
        #pragma unroll 4
        for (int j = 0; j < 64; j++)
            mf[j] = ((bits >> j) & 1ull) ? 1.0f : 0.0f;
    }

    // rank targets per bin: pb_k = pos of rank start_k, pe_k = pos of rank end_k-1
    if (tid < BINS) {
        int k = tid;
        int start = (k * L) / BINS;                    // 32-bit ops, L<=16384
        int end   = ((k + 1) * L + BINS - 1) / BINS;
        int denom = max(end - start, 1);
        g_inv[seg * BINS + k] = 1.0f / (float)denom;
        s_t0[k] = start;
        s_t1[k] = end - 1;
        s_pb[k] = NP;                                  // empty-bin defaults
        s_pe[k] = -1;
    }
    __syncthreads();

    if (cnt > 0) {
        #pragma unroll
        for (int k = 0; k < BINS; k++) {
            int t0 = s_t0[k], t1 = s_t1[k];
            if (t0 >= excl && t0 < excl + cnt)
                s_pb[k] = base_p + nth_set_bit64(bits, t0 - excl);
            if (t1 >= excl && t1 < excl + cnt)
                s_pe[k] = base_p + nth_set_bit64(bits, t1 - excl);
        }
    }
    __syncthreads();

    if (tid < BINS) {
        g_pb[seg * BINS + tid] = s_pb[tid];
        g_pe[seg * BINS + tid] = s_pe[tid];
    }
}

// ---------------- kernel 2: float4 masked segment sums -----------------------
// grid (NC, NSEG), 256 threads. Interior of each bin interval: float4 x and
// float4 mask (L1-resident), 4 FFMA per 16B. <=3 head + <=3 tail scalars/bin.
__global__ void k_pool(const float* __restrict__ xs) {
    const int c = blockIdx.x, seg = blockIdx.y;
    const int tid = threadIdx.x, lane = tid & 31;
    __shared__ int   spb[BINS], spe[BINS];
    __shared__ float sinv[BINS];
    __shared__ float sbins[BINS];
    if (tid < BINS) {
        spb [tid] = g_pb [seg * BINS + tid];
        spe [tid] = g_pe [seg * BINS + tid];
        sinv[tid] = g_inv[seg * BINS + tid];
        sbins[tid] = 0.0f;
    }
    __syncthreads();

    const float*  __restrict__ xr = xs + ((size_t)seg * NC + c) * NP;
    const float*  __restrict__ mr = g_maskf + (size_t)seg * NP;
    const float4* __restrict__ x4 = (const float4*)xr;
    const float4* __restrict__ m4 = (const float4*)mr;

    float accs[BINS];
    #pragma unroll
    for (int k = 0; k < BINS; k++) {
        float acc = 0.0f;
        const int b = spb[k], e = spe[k];
        if (b <= e) {
            int fb = (b + 3) & ~3; if (fb > e + 1) fb = e + 1;
            int fe = (e + 1) & ~3; if (fe < fb) fe = fb;
            // head scalars [b, fb)
            if (tid < fb - b) { int p = b + tid; acc += xr[p] * mr[p]; }
            // tail scalars [fe, e]
            if (tid >= 8 && tid - 8 < (e + 1 - fe)) { int p = fe + tid - 8; acc += xr[p] * mr[p]; }
            // interior float4s
            const int q0 = fb >> 2, q1 = fe >> 2;
            for (int t = q0 + tid; t < q1; t += 256) {
                float4 v = x4[t];
                float4 m = m4[t];
                acc += v.x * m.x + v.y * m.y + v.z * m.z + v.w * m.w;
            }
        }
        accs[k] = acc;
    }

    #pragma unroll
    for (int k = 0; k < BINS; k++) {
        float acc = accs[k];
        #pragma unroll
        for (int off = 16; off; off >>= 1) acc += __shfl_down_sync(0xffffffffu, acc, off);
        if (lane == 0) atomicAdd(&sbins[k], acc);
    }
    __syncthreads();
    if (tid < BINS)
        g_ys[((size_t)seg * NC + c) * BINS + tid] = sbins[tid] * sinv[tid];
}

// ---------------- fcA: block-per-row, full load batch up front ---------------
__global__ void k_fcA(const float* __restrict__ W, const float* __restrict__ b) {
    const int row = blockIdx.x;                 // 0..12287
    const int seg = row >> 11;
    const int tid = threadIdx.x;
    const int lane = tid & 31, wid = tid >> 5;

    const float4* __restrict__ W4 = (const float4*)(W + (size_t)row * 8192);
    const float4* __restrict__ x4 = (const float4*)(g_ys + (size_t)seg * 8192);

    float4 w0 = W4[0 * 256 + tid];
    float4 w1 = W4[1 * 256 + tid];
    float4 w2 = W4[2 * 256 + tid];
    float4 w3 = W4[3 * 256 + tid];
    float4 w4 = W4[4 * 256 + tid];
    float4 w5 = W4[5 * 256 + tid];
    float4 w6 = W4[6 * 256 + tid];
    float4 w7 = W4[7 * 256 + tid];

    float acc0 = 0.f, acc1 = 0.f;
    {
        float4 v;
        v = x4[0 * 256 + tid]; acc0 += w0.x*v.x + w0.y*v.y + w0.z*v.z + w0.w*v.w;
        v = x4[1 * 256 + tid]; acc1 += w1.x*v.x + w1.y*v.y + w1.z*v.z + w1.w*v.w;
        v = x4[2 * 256 + tid]; acc0 += w2.x*v.x + w2.y*v.y + w2.z*v.z + w2.w*v.w;
        v = x4[3 * 256 + tid]; acc1 += w3.x*v.x + w3.y*v.y + w3.z*v.z + w3.w*v.w;
        v = x4[4 * 256 + tid]; acc0 += w4.x*v.x + w4.y*v.y + w4.z*v.z + w4.w*v.w;
        v = x4[5 * 256 + tid]; acc1 += w5.x*v.x + w5.y*v.y + w5.z*v.z + w5.w*v.w;
        v = x4[6 * 256 + tid]; acc0 += w6.x*v.x + w6.y*v.y + w6.z*v.z + w6.w*v.w;
        v = x4[7 * 256 + tid]; acc1 += w7.x*v.x + w7.y*v.y + w7.z*v.z + w7.w*v.w;
    }
    float acc = acc0 + acc1;
    #pragma unroll
    for (int off = 16; off; off >>= 1) acc += __shfl_down_sync(0xffffffffu, acc, off);

    __shared__ float ssum[8];
    if (lane == 0) ssum[wid] = acc;
    __syncthreads();
    if (tid == 0) {
        float s = ssum[0] + ssum[1] + ssum[2] + ssum[3]
                + ssum[4] + ssum[5] + ssum[6] + ssum[7];
        g_wA[row] = s + b[row];
    }
}

// ---------------- fcB: block-per-row (same pattern, 2048 wide) ---------------
__global__ void k_fcB(const float* __restrict__ W, const float* __restrict__ b) {
    const int row = blockIdx.x;                 // 0..3071
    const int seg = row >> 9;
    const int tid = threadIdx.x;
    const int lane = tid & 31, wid = tid >> 5;

    const float4* __restrict__ W4 = (const float4*)(W + (size_t)row * 2048);
    const float4* __restrict__ x4 = (const float4*)(g_wA + (size_t)seg * 2048);

    float4 w0 = W4[tid];
    float4 w1 = W4[256 + tid];
    float4 v0 = x4[tid];
    float4 v1 = x4[256 + tid];
    float acc = w0.x*v0.x + w0.y*v0.y + w0.z*v0.z + w0.w*v0.w
              + w1.x*v1.x + w1.y*v1.y + w1.z*v1.z + w1.w*v1.w;

    #pragma unroll
    for (int off = 16; off; off >>= 1) acc += __shfl_down_sync(0xffffffffu, acc, off);
    __shared__ float ssum[8];
    if (lane == 0) ssum[wid] = acc;
    __syncthreads();
    if (tid == 0) {
        float s = ssum[0] + ssum[1] + ssum[2] + ssum[3]
                + ssum[4] + ssum[5] + ssum[6] + ssum[7];
        g_wB[row] = s + b[row];
    }
}

// ---------------- generic GEMV (warp per row) for fcC ------------------------
template <int NDIM>
__global__ void k_gemv(const float* __restrict__ W, const float* __restrict__ xin,
                       const float* __restrict__ b, float* __restrict__ y,
                       int rows_per_seg, int x_seg_stride, int y_seg_stride) {
    const int gwarp = (blockIdx.x * blockDim.x + threadIdx.x) >> 5;
    const int lane  = threadIdx.x & 31;
    const int row   = gwarp;
    const int seg   = row / rows_per_seg;
    const int m     = row - seg * rows_per_seg;

    const float4* W4 = (const float4*)(W + (size_t)row * NDIM);
    const float4* x4 = (const float4*)(xin + (size_t)seg * x_seg_stride);

    float acc = 0.0f;
    #pragma unroll 4
    for (int i = lane; i < NDIM / 4; i += 32) {
        float4 w = W4[i];
        float4 v = x4[i];
        acc += w.x * v.x + w.y * v.y + w.z * v.z + w.w * v.w;
    }
    #pragma unroll
    for (int off = 16; off; off >>= 1) acc += __shfl_down_sync(0xffffffffu, acc, off);
    if (lane == 0) y[(size_t)seg * y_seg_stride + m] = acc + b[row];
}

// ---------------- final cascade ----------------------------------------------
__global__ void k_final(const float* __restrict__ p1w, const float* __restrict__ p1b,
                        const float* __restrict__ p2w, const float* __restrict__ p2b,
                        const float* __restrict__ p3w, const float* __restrict__ p3b,
                        float* __restrict__ out) {
    const int seg = blockIdx.x;
    const int tid = threadIdx.x, lane = tid & 31, wid = tid >> 5; // 8 warps
    __shared__ float w0s[512], w1s[256], w2s[128];
    float* o = out + seg * 960;

    for (int i = tid; i < 512; i += 256) w0s[i] = o[i];
    __syncthreads();

    for (int m = wid; m < 256; m += 8) {
        float acc = 0.0f;
        for (int n = lane; n < 512; n += 32) acc += p1w[m * 512 + n] * w0s[n];
        #pragma unroll
        for (int off = 16; off; off >>= 1) acc += __shfl_down_sync(0xffffffffu, acc, off);
        if (lane == 0) { float v = acc + p1b[m]; w1s[m] = v; o[512 + m] = v; }
    }
    __syncthreads();

    for (int m = wid; m < 128; m += 8) {
        float acc = 0.0f;
        for (int n = lane; n < 256; n += 32) acc += p2w[m * 256 + n] * w1s[n];
        #pragma unroll
        for (int off = 16; off; off >>= 1) acc += __shfl_down_sync(0xffffffffu, acc, off);
        if (lane == 0) { float v = acc + p2b[m]; w2s[m] = v; o[768 + m] = v; }
    }
    __syncthreads();

    for (int m = wid; m < 64; m += 8) {
        float acc = 0.0f;
        for (int n = lane; n < 128; n += 32) acc += p3w[m * 128 + n] * w2s[n];
        #pragma unroll
        for (int off = 16; off; off >>= 1) acc += __shfl_down_sync(0xffffffffu, acc, off);
        if (lane == 0) o[896 + m] = acc + p3b[m];
    }
}

// ---------------- launch ------------------------------------------------------
extern "C" void kernel_launch(void* const* d_in, const int* in_sizes, int n_in,
                              void* d_out, int out_size) {
    const float* xs      = (const float*)d_in[0];
    const int*   parsing = (const int*)  d_in[1];
    const float* fcA_w   = (const float*)d_in[2];
    const float* fcA_b   = (const float*)d_in[3];
    const float* fcB_w   = (const float*)d_in[4];
    const float* fcB_b   = (const float*)d_in[5];
    const float* fcC_w   = (const float*)d_in[6];
    const float* fcC_b   = (const float*)d_in[7];
    const float* p1_w    = (const float*)d_in[8];
    const float* p1_b    = (const float*)d_in[9];
    const float* p2_w    = (const float*)d_in[10];
    const float* p2_b    = (const float*)d_in[11];
    const float* p3_w    = (const float*)d_in[12];
    const float* p3_b    = (const float*)d_in[13];
    float* out = (float*)d_out;                     // [6,1,960]

    float* wBp; cudaGetSymbolAddress((void**)&wBp, g_wB);

    // 0,1) nops — keep the fixed ncu capture slot (4th launch) on k_pool
    k_nop<<<1, 32>>>();
    k_nop<<<1, 32>>>();

    // 2) mask floats + scan + bin intervals (division-free)
    k_scan<<<NSEG, 256>>>(parsing);

    // 3) float4 masked segment pooling (201 MB)
    k_pool<<<dim3(NC, NSEG), 256>>>(xs);

    // 4) fcA: block-per-row (402 MB)
    k_fcA<<<NSEG * 2048, 256>>>(fcA_w, fcA_b);

    // 5) fcB: block-per-row (25 MB)
    k_fcB<<<NSEG * 512, 256>>>(fcB_w, fcB_b);

    // 6) fcC: 6x[512x512] -> out[seg*960 + 0..511] (w0)
    k_gemv<512><<<(NSEG * 512) / 8, 256>>>(fcC_w, wBp, fcC_b, out, 512, 512, 960);

    // 7) p1/p2/p3 cascade -> out[seg*960 + 512..959]
    k_final<<<NSEG, 256>>>(p1_w, p1_b, p2_w, p2_b, p3_w, p3_b, out);
}

// round 6
// speedup vs baseline: 1.2289x; 1.2289x over previous
#include <cuda_runtime.h>
#include <stdint.h>

#define NSEG 6
#define NC   512
#define NP   16384   // 128*128
#define BINS 16

// ---------------- scratch (__device__ globals, no allocation) ----------------
__device__ uint32_t g_mbits[NSEG * 512];       // mask bits, word p>>5, bit p&31
__device__ int      g_pb  [NSEG * BINS];       // bin position interval begin (incl)
__device__ int      g_pe  [NSEG * BINS];       // bin position interval end   (incl)
__device__ float    g_inv [NSEG * BINS];       // 1/denom per (seg,bin)
__device__ float    g_ys  [NSEG * NC * BINS];  // pooled features
__device__ float    g_wA  [NSEG * 2048];
__device__ float    g_wB  [NSEG * 512];

// ---------------- n-th set bit (n < popc(m)) ---------------------------------
__device__ __forceinline__ int nth_set_bit32(unsigned m, int n) {
    for (int i = 0; i < n; i++) m &= m - 1;    // clear n lowest set bits
    return __ffs(m) - 1;
}

// ---------------- kernel 1: mask + scan + bin intervals ----------------------
// grid <<<6, 1024>>>, 16 positions/thread — no long serial loops, no divisions
// by runtime values, boundary ranks via <=16-step bit-clear on a 16-bit word.
__global__ void k_scan(const int* __restrict__ parsing) {
    const int seg = blockIdx.x;
    const int tid = threadIdx.x;              // 0..1023
    const int lane = tid & 31, wid = tid >> 5;
    const int* ps = parsing + seg * 65536;    // [256,256] plane

    const int base_p = tid * 16;
    unsigned bits = 0;
    #pragma unroll
    for (int j = 0; j < 16; j++) {
        int p = base_p + j;
        int h = p >> 7, w = p & 127;
        if (ps[h * 512 + w * 2] != 0) bits |= (1u << j);   // nearest 256->128: (2h,2w)
    }
    const int cnt = __popc(bits);

    __shared__ int warp_tot[32];
    __shared__ int warp_off[32];
    __shared__ int sL;
    __shared__ int s_pb[BINS], s_pe[BINS];
    __shared__ int s_t0[BINS], s_t1[BINS];

    // 1024-thread inclusive scan of per-thread counts
    int x = cnt;
    #pragma unroll
    for (int off = 1; off < 32; off <<= 1) {
        int y = __shfl_up_sync(0xffffffffu, x, off);
        if (lane >= off) x += y;
    }
    if (lane == 31) warp_tot[wid] = x;
    if (tid < BINS) { s_pb[tid] = NP; s_pe[tid] = -1; }   // empty-bin defaults
    __syncthreads();
    if (wid == 0) {
        int v = warp_tot[lane];
        int inc = v;
        #pragma unroll
        for (int off = 1; off < 32; off <<= 1) {
            int y = __shfl_up_sync(0xffffffffu, inc, off);
            if (lane >= off) inc += y;
        }
        warp_off[lane] = inc - v;             // exclusive warp offsets
        if (lane == 31) sL = inc;
    }
    __syncthreads();
    const int excl = warp_off[wid] + x - cnt;
    const int L = sL;

    // pack mask words: two threads (16 bits each) per uint32
    {
        unsigned hi = __shfl_down_sync(0xffffffffu, bits, 1);
        if ((tid & 1) == 0)
            g_mbits[seg * 512 + (tid >> 1)] = bits | (hi << 16);
    }

    // per-bin rank targets (32-bit arithmetic; L <= 16384)
    if (tid < BINS) {
        int k = tid;
        int start = (k * L) / BINS;
        int end   = ((k + 1) * L + BINS - 1) / BINS;
        int denom = max(end - start, 1);
        g_inv[seg * BINS + k] = 1.0f / (float)denom;
        s_t0[k] = start;
        s_t1[k] = end - 1;
    }
    __syncthreads();

    if (cnt > 0) {
        const int lo = excl, hi = excl + cnt;
        #pragma unroll
        for (int k = 0; k < BINS; k++) {
            int t0 = s_t0[k];
            if (t0 >= lo && t0 < hi) s_pb[k] = base_p + nth_set_bit32(bits, t0 - lo);
            int t1 = s_t1[k];
            if (t1 >= lo && t1 < hi) s_pe[k] = base_p + nth_set_bit32(bits, t1 - lo);
        }
    }
    __syncthreads();

    if (tid < BINS) {
        g_pb[seg * BINS + tid] = s_pb[tid];
        g_pe[seg * BINS + tid] = s_pe[tid];
    }
}

// ---------------- kernel 2: masked segment sums (R4 form, measured 66.8us) ---
__global__ void k_pool(const float* __restrict__ xs) {
    const int c = blockIdx.x, seg = blockIdx.y;
    const int tid = threadIdx.x, lane = tid & 31;
    __shared__ uint32_t smb[512];
    __shared__ int   spb[BINS], spe[BINS];
    __shared__ float sinv[BINS];
    __shared__ float sbins[BINS];

    smb[tid]       = g_mbits[seg * 512 + tid];
    smb[tid + 256] = g_mbits[seg * 512 + 256 + tid];
    if (tid < BINS) {
        spb [tid] = g_pb [seg * BINS + tid];
        spe [tid] = g_pe [seg * BINS + tid];
        sinv[tid] = g_inv[seg * BINS + tid];
        sbins[tid] = 0.0f;
    }
    __syncthreads();

    const float* __restrict__ x = xs + ((size_t)seg * NC + c) * NP;

    float accs[BINS];
    #pragma unroll
    for (int k = 0; k < BINS; k++) {
        float acc = 0.0f;
        const int e = spe[k];
        for (int p = spb[k] + tid; p <= e; p += 256) {
            float m = ((smb[p >> 5] >> (p & 31)) & 1u) ? 1.0f : 0.0f;
            acc += x[p] * m;
        }
        accs[k] = acc;
    }

    #pragma unroll
    for (int k = 0; k < BINS; k++) {
        float acc = accs[k];
        #pragma unroll
        for (int off = 16; off; off >>= 1) acc += __shfl_down_sync(0xffffffffu, acc, off);
        if (lane == 0) atomicAdd(&sbins[k], acc);
    }
    __syncthreads();
    if (tid < BINS)
        g_ys[((size_t)seg * NC + c) * BINS + tid] = sbins[tid] * sinv[tid];
}

// ---------------- fcA: block-per-row, full load batch up front ---------------
__global__ void k_fcA(const float* __restrict__ W, const float* __restrict__ b) {
    const int row = blockIdx.x;                 // 0..12287
    const int seg = row >> 11;
    const int tid = threadIdx.x;
    const int lane = tid & 31, wid = tid >> 5;

    const float4* __restrict__ W4 = (const float4*)(W + (size_t)row * 8192);
    const float4* __restrict__ x4 = (const float4*)(g_ys + (size_t)seg * 8192);

    float4 w0 = W4[0 * 256 + tid];
    float4 w1 = W4[1 * 256 + tid];
    float4 w2 = W4[2 * 256 + tid];
    float4 w3 = W4[3 * 256 + tid];
    float4 w4 = W4[4 * 256 + tid];
    float4 w5 = W4[5 * 256 + tid];
    float4 w6 = W4[6 * 256 + tid];
    float4 w7 = W4[7 * 256 + tid];

    float acc0 = 0.f, acc1 = 0.f;
    {
        float4 v;
        v = x4[0 * 256 + tid]; acc0 += w0.x*v.x + w0.y*v.y + w0.z*v.z + w0.w*v.w;
        v = x4[1 * 256 + tid]; acc1 += w1.x*v.x + w1.y*v.y + w1.z*v.z + w1.w*v.w;
        v = x4[2 * 256 + tid]; acc0 += w2.x*v.x + w2.y*v.y + w2.z*v.z + w2.w*v.w;
        v = x4[3 * 256 + tid]; acc1 += w3.x*v.x + w3.y*v.y + w3.z*v.z + w3.w*v.w;
        v = x4[4 * 256 + tid]; acc0 += w4.x*v.x + w4.y*v.y + w4.z*v.z + w4.w*v.w;
        v = x4[5 * 256 + tid]; acc1 += w5.x*v.x + w5.y*v.y + w5.z*v.z + w5.w*v.w;
        v = x4[6 * 256 + tid]; acc0 += w6.x*v.x + w6.y*v.y + w6.z*v.z + w6.w*v.w;
        v = x4[7 * 256 + tid]; acc1 += w7.x*v.x + w7.y*v.y + w7.z*v.z + w7.w*v.w;
    }
    float acc = acc0 + acc1;
    #pragma unroll
    for (int off = 16; off; off >>= 1) acc += __shfl_down_sync(0xffffffffu, acc, off);

    __shared__ float ssum[8];
    if (lane == 0) ssum[wid] = acc;
    __syncthreads();
    if (tid == 0) {
        float s = ssum[0] + ssum[1] + ssum[2] + ssum[3]
                + ssum[4] + ssum[5] + ssum[6] + ssum[7];
        g_wA[row] = s + b[row];
    }
}

// ---------------- fcB: block-per-row (same pattern, 2048 wide) ---------------
__global__ void k_fcB(const float* __restrict__ W, const float* __restrict__ b) {
    const int row = blockIdx.x;                 // 0..3071
    const int seg = row >> 9;
    const int tid = threadIdx.x;
    const int lane = tid & 31, wid = tid >> 5;

    const float4* __restrict__ W4 = (const float4*)(W + (size_t)row * 2048);
    const float4* __restrict__ x4 = (const float4*)(g_wA + (size_t)seg * 2048);

    float4 w0 = W4[tid];
    float4 w1 = W4[256 + tid];
    float4 v0 = x4[tid];
    float4 v1 = x4[256 + tid];
    float acc = w0.x*v0.x + w0.y*v0.y + w0.z*v0.z + w0.w*v0.w
              + w1.x*v1.x + w1.y*v1.y + w1.z*v1.z + w1.w*v1.w;

    #pragma unroll
    for (int off = 16; off; off >>= 1) acc += __shfl_down_sync(0xffffffffu, acc, off);
    __shared__ float ssum[8];
    if (lane == 0) ssum[wid] = acc;
    __syncthreads();
    if (tid == 0) {
        float s = ssum[0] + ssum[1] + ssum[2] + ssum[3]
                + ssum[4] + ssum[5] + ssum[6] + ssum[7];
        g_wB[row] = s + b[row];
    }
}

// ---------------- generic GEMV (warp per row) for fcC ------------------------
template <int NDIM>
__global__ void k_gemv(const float* __restrict__ W, const float* __restrict__ xin,
                       const float* __restrict__ b, float* __restrict__ y,
                       int rows_per_seg, int x_seg_stride, int y_seg_stride) {
    const int gwarp = (blockIdx.x * blockDim.x + threadIdx.x) >> 5;
    const int lane  = threadIdx.x & 31;
    const int row   = gwarp;
    const int seg   = row / rows_per_seg;
    const int m     = row - seg * rows_per_seg;

    const float4* W4 = (const float4*)(W + (size_t)row * NDIM);
    const float4* x4 = (const float4*)(xin + (size_t)seg * x_seg_stride);

    float acc = 0.0f;
    #pragma unroll 4
    for (int i = lane; i < NDIM / 4; i += 32) {
        float4 w = W4[i];
        float4 v = x4[i];
        acc += w.x * v.x + w.y * v.y + w.z * v.z + w.w * v.w;
    }
    #pragma unroll
    for (int off = 16; off; off >>= 1) acc += __shfl_down_sync(0xffffffffu, acc, off);
    if (lane == 0) y[(size_t)seg * y_seg_stride + m] = acc + b[row];
}

// ---------------- final cascade ----------------------------------------------
__global__ void k_final(const float* __restrict__ p1w, const float* __restrict__ p1b,
                        const float* __restrict__ p2w, const float* __restrict__ p2b,
                        const float* __restrict__ p3w, const float* __restrict__ p3b,
                        float* __restrict__ out) {
    const int seg = blockIdx.x;
    const int tid = threadIdx.x, lane = tid & 31, wid = tid >> 5; // 8 warps
    __shared__ float w0s[512], w1s[256], w2s[128];
    float* o = out + seg * 960;

    for (int i = tid; i < 512; i += 256) w0s[i] = o[i];
    __syncthreads();

    for (int m = wid; m < 256; m += 8) {
        float acc = 0.0f;
        for (int n = lane; n < 512; n += 32) acc += p1w[m * 512 + n] * w0s[n];
        #pragma unroll
        for (int off = 16; off; off >>= 1) acc += __shfl_down_sync(0xffffffffu, acc, off);
        if (lane == 0) { float v = acc + p1b[m]; w1s[m] = v; o[512 + m] = v; }
    }
    __syncthreads();

    for (int m = wid; m < 128; m += 8) {
        float acc = 0.0f;
        for (int n = lane; n < 256; n += 32) acc += p2w[m * 256 + n] * w1s[n];
        #pragma unroll
        for (int off = 16; off; off >>= 1) acc += __shfl_down_sync(0xffffffffu, acc, off);
        if (lane == 0) { float v = acc + p2b[m]; w2s[m] = v; o[768 + m] = v; }
    }
    __syncthreads();

    for (int m = wid; m < 64; m += 8) {
        float acc = 0.0f;
        for (int n = lane; n < 128; n += 32) acc += p3w[m * 128 + n] * w2s[n];
        #pragma unroll
        for (int off = 16; off; off >>= 1) acc += __shfl_down_sync(0xffffffffu, acc, off);
        if (lane == 0) o[896 + m] = acc + p3b[m];
    }
}

// ---------------- launch ------------------------------------------------------
extern "C" void kernel_launch(void* const* d_in, const int* in_sizes, int n_in,
                              void* d_out, int out_size) {
    const float* xs      = (const float*)d_in[0];
    const int*   parsing = (const int*)  d_in[1];
    const float* fcA_w   = (const float*)d_in[2];
    const float* fcA_b   = (const float*)d_in[3];
    const float* fcB_w   = (const float*)d_in[4];
    const float* fcB_b   = (const float*)d_in[5];
    const float* fcC_w   = (const float*)d_in[6];
    const float* fcC_b   = (const float*)d_in[7];
    const float* p1_w    = (const float*)d_in[8];
    const float* p1_b    = (const float*)d_in[9];
    const float* p2_w    = (const float*)d_in[10];
    const float* p2_b    = (const float*)d_in[11];
    const float* p3_w    = (const float*)d_in[12];
    const float* p3_b    = (const float*)d_in[13];
    float* out = (float*)d_out;                     // [6,1,960]

    float* wBp; cudaGetSymbolAddress((void**)&wBp, g_wB);

    // 1) mask + scan + bin intervals (1024 threads, 16 pos/thread, div-free)
    k_scan<<<NSEG, 1024>>>(parsing);

    // 2) masked segment pooling (201 MB) — R4 form
    k_pool<<<dim3(NC, NSEG), 256>>>(xs);

    // 3) fcA: block-per-row (402 MB)
    k_fcA<<<NSEG * 2048, 256>>>(fcA_w, fcA_b);

    // 4) fcB: block-per-row (25 MB) — lands in the ncu capture slot
    k_fcB<<<NSEG * 512, 256>>>(fcB_w, fcB_b);

    // 5) fcC: 6x[512x512] -> out[seg*960 + 0..511] (w0)
    k_gemv<512><<<(NSEG * 512) / 8, 256>>>(fcC_w, wBp, fcC_b, out, 512, 512, 960);

    // 6) p1/p2/p3 cascade -> out[seg*960 + 512..959]
    k_final<<<NSEG, 256>>>(p1_w, p1_b, p2_w, p2_b, p3_w, p3_b, out);
}